// round 9
// baseline (speedup 1.0000x reference)
#include <cuda_runtime.h>
#include <cuda_fp16.h>
#include <cstdint>

// Problem constants
#define BDIM 2
#define LSEQ 8192
#define CDIM 512
#define KWIN 17
#define HALFK 8
#define NTOK (BDIM * LSEQ)      // 16384

// ---------------------------------------------------------------------------
// Scratch (__device__ globals; no cudaMalloc allowed)
// ---------------------------------------------------------------------------
__device__ __half  g_qkvh[(size_t)NTOK * 3 * CDIM];    // 48 MB fp16 qkv
__device__ __half  g_xhi[(size_t)NTOK * CDIM];
__device__ __half  g_xlo[(size_t)NTOK * CDIM];
__device__ __half  g_ahi[(size_t)NTOK * CDIM];
__device__ __half  g_alo[(size_t)NTOK * CDIM];
__device__ __half  g_wqhi[(size_t)3 * CDIM * CDIM];    // [1536][512] = w_qkv^T hi
__device__ __half  g_wohi[(size_t)CDIM * CDIM];        // [512][512]  = w_out^T hi

// ---------------------------------------------------------------------------
// helpers
// ---------------------------------------------------------------------------
__device__ __forceinline__ uint32_t smem_u32(const void* p) {
    uint32_t a;
    asm("{ .reg .u64 t; cvta.to.shared.u64 t, %1; cvt.u32.u64 %0, t; }" : "=r"(a) : "l"(p));
    return a;
}
__device__ __forceinline__ void cp16(uint32_t dst, const void* src) {
    asm volatile("cp.async.cg.shared.global [%0], [%1], 16;" :: "r"(dst), "l"(src));
}
__device__ __forceinline__ void ldsm_x4(uint32_t* r, uint32_t addr) {
    asm volatile("ldmatrix.sync.aligned.m8n8.x4.shared.b16 {%0,%1,%2,%3}, [%4];"
                 : "=r"(r[0]), "=r"(r[1]), "=r"(r[2]), "=r"(r[3]) : "r"(addr));
}
__device__ __forceinline__ void ldsm_x2(uint32_t* r, uint32_t addr) {
    asm volatile("ldmatrix.sync.aligned.m8n8.x2.shared.b16 {%0,%1}, [%2];"
                 : "=r"(r[0]), "=r"(r[1]) : "r"(addr));
}
__device__ __forceinline__ void mma_f16(float* c, const uint32_t* a, const uint32_t* b) {
    asm volatile(
        "mma.sync.aligned.m16n8k16.row.col.f32.f16.f16.f32 "
        "{%0,%1,%2,%3}, {%4,%5,%6,%7}, {%8,%9}, {%0,%1,%2,%3};"
        : "+f"(c[0]), "+f"(c[1]), "+f"(c[2]), "+f"(c[3])
        : "r"(a[0]), "r"(a[1]), "r"(a[2]), "r"(a[3]), "r"(b[0]), "r"(b[1]));
}
#define CPWAIT(N) asm volatile("cp.async.wait_group %0;" :: "n"(N))

__device__ __forceinline__ void unpack8(uint4 u, float* f) {
    const __half2* h = (const __half2*)&u;
    #pragma unroll
    for (int t = 0; t < 4; t++) {
        float2 v = __half22float2(h[t]);
        f[2 * t] = v.x;
        f[2 * t + 1] = v.y;
    }
}

// ---------------------------------------------------------------------------
// 2-term split-fp16 GEMM:  C = (Ahi + Alo) @ Bhi^T   (fp32 accum, OutT store)
// Block 128x128, 8 warps (2x4), warp 64x32.  BK=32, 3-stage cp.async pipeline
// with ONE __syncthreads per stage (load for s+2 targets the buffer consumed
// at s-1, already protected by the top-of-stage barrier).  2 CTAs/SM.
// PITCH=80 -> conflict-free ldmatrix.
// ---------------------------------------------------------------------------
#define GK       512
#define BK       32
#define NSTG     (GK / BK)          // 16
#define NBUF     3
#define PITCH    80
#define A_SZ     (128 * PITCH)      // 10240
#define STG_SZ   (3 * A_SZ)         // Ahi | Alo | Bhi = 30720
#define GEMM_SMEM (NBUF * STG_SZ)   // 92160

template <typename OutT>
__global__ __launch_bounds__(256, 2) void gemm_mma(
    const __half* __restrict__ Ahi, const __half* __restrict__ Alo,
    const __half* __restrict__ Bhi,
    OutT* __restrict__ C, int Ntot)
{
    extern __shared__ char smem[];
    const uint32_t sb = smem_u32(smem);
    const int tid  = threadIdx.x;
    const int wid  = tid >> 5;
    const int lane = tid & 31;
    const int bm = blockIdx.y * 128;
    const int bn = blockIdx.x * 128;
    const int warp_m = (wid >> 2) * 64;
    const int warp_n = (wid & 3) * 32;

    // loader: 128 rows x 4 chunks(16B) per matrix = 512 chunks / 256 thr = 2 ea
    auto load_stage = [&](int s, int b) {
        const int k0 = s * BK;
        const uint32_t buf = sb + (uint32_t)b * STG_SZ;
        #pragma unroll
        for (int r = 0; r < 2; r++) {
            const int i   = tid + 256 * r;
            const int row = i >> 2;
            const int c16 = (i & 3) * 16;
            const uint32_t off = (uint32_t)(row * PITCH + c16);
            const size_t ga = (size_t)(bm + row) * GK + k0 + (c16 >> 1);
            const size_t gb = (size_t)(bn + row) * GK + k0 + (c16 >> 1);
            cp16(buf + off,            Ahi + ga);
            cp16(buf + A_SZ + off,     Alo + ga);
            cp16(buf + 2 * A_SZ + off, Bhi + gb);
        }
        asm volatile("cp.async.commit_group;" ::: "memory");
    };

    float acc[4][4][4];
    #pragma unroll
    for (int mi = 0; mi < 4; mi++)
        #pragma unroll
        for (int ni = 0; ni < 4; ni++)
            #pragma unroll
            for (int f = 0; f < 4; f++) acc[mi][ni][f] = 0.f;

    const uint32_t aLane = (uint32_t)((warp_m + (lane & 15)) * PITCH + ((lane >> 4) & 1) * 16);
    const uint32_t bLane = (uint32_t)((warp_n + (lane & 7)) * PITCH + ((lane >> 3) & 1) * 16);

    load_stage(0, 0);
    load_stage(1, 1);

    for (int s = 0; s < NSTG; s++) {
        const int b = s % NBUF;
        if (s + 1 < NSTG) CPWAIT(1);
        else              CPWAIT(0);
        __syncthreads();
        // issue next-next stage loads now; they overlap this stage's MMAs.
        // target buffer (s+2)%3 == (s-1)%3 was consumed at stage s-1 and the
        // barrier above guarantees every warp is past it.
        if (s + 2 < NSTG) load_stage(s + 2, (s + 2) % NBUF);

        const uint32_t buf = sb + (uint32_t)b * STG_SZ;
        #pragma unroll
        for (int kk = 0; kk < 2; kk++) {
            const uint32_t ko = (uint32_t)(kk * 32);
            uint32_t ah[4][4], al[4][4], bh[4][2];
            #pragma unroll
            for (int mi = 0; mi < 4; mi++)
                ldsm_x4(ah[mi], buf + aLane + (uint32_t)(mi * 16 * PITCH) + ko);
            #pragma unroll
            for (int mi = 0; mi < 4; mi++)
                ldsm_x4(al[mi], buf + A_SZ + aLane + (uint32_t)(mi * 16 * PITCH) + ko);
            #pragma unroll
            for (int ni = 0; ni < 4; ni++)
                ldsm_x2(bh[ni], buf + 2 * A_SZ + bLane + (uint32_t)(ni * 8 * PITCH) + ko);
            #pragma unroll
            for (int mi = 0; mi < 4; mi++)
                #pragma unroll
                for (int ni = 0; ni < 4; ni++) {
                    mma_f16(acc[mi][ni], ah[mi], bh[ni]);
                    mma_f16(acc[mi][ni], al[mi], bh[ni]);
                }
        }
    }

    const int er = lane >> 2;
    const int ec = (lane & 3) * 2;
    #pragma unroll
    for (int mi = 0; mi < 4; mi++) {
        #pragma unroll
        for (int ni = 0; ni < 4; ni++) {
            OutT* p0 = C + (size_t)(bm + warp_m + mi * 16 + er) * Ntot + bn + warp_n + ni * 8 + ec;
            if constexpr (sizeof(OutT) == 2) {
                *(__half2*)p0 = __floats2half2_rn(acc[mi][ni][0], acc[mi][ni][1]);
                *(__half2*)(p0 + (size_t)8 * Ntot) = __floats2half2_rn(acc[mi][ni][2], acc[mi][ni][3]);
            } else {
                *(float2*)p0                      = make_float2(acc[mi][ni][0], acc[mi][ni][1]);
                *(float2*)(p0 + (size_t)8 * Ntot) = make_float2(acc[mi][ni][2], acc[mi][ni][3]);
            }
        }
    }
}

// ---------------------------------------------------------------------------
// fp32 -> (hi, lo) fp16 split, elementwise
// ---------------------------------------------------------------------------
__global__ __launch_bounds__(256) void split_kernel(const float* __restrict__ src,
                                                    __half* __restrict__ hi,
                                                    __half* __restrict__ lo)
{
    const size_t i = ((size_t)blockIdx.x * blockDim.x + threadIdx.x) * 4;
    float4 v = *(const float4*)(src + i);
    __half h0 = __float2half(v.x), h1 = __float2half(v.y);
    __half h2 = __float2half(v.z), h3 = __float2half(v.w);
    __half l0 = __float2half(v.x - __half2float(h0));
    __half l1 = __float2half(v.y - __half2float(h1));
    __half l2 = __float2half(v.z - __half2float(h2));
    __half l3 = __float2half(v.w - __half2float(h3));
    *(__half2*)(hi + i)     = __halves2half2(h0, h1);
    *(__half2*)(hi + i + 2) = __halves2half2(h2, h3);
    *(__half2*)(lo + i)     = __halves2half2(l0, l1);
    *(__half2*)(lo + i + 2) = __halves2half2(l2, l3);
}

// ---------------------------------------------------------------------------
// weight transpose (hi only): w[K,N] fp32 -> hiT [N,K] fp16
// ---------------------------------------------------------------------------
__global__ __launch_bounds__(256) void wsplit_kernel(const float* __restrict__ w,
                                                     __half* __restrict__ hiT,
                                                     int K, int N)
{
    __shared__ float t[32][33];
    const int k0 = blockIdx.y * 32;
    const int n0 = blockIdx.x * 32;
    const int tx = threadIdx.x, ty = threadIdx.y;
    #pragma unroll
    for (int i = ty; i < 32; i += 8)
        t[i][tx] = w[(size_t)(k0 + i) * N + n0 + tx];
    __syncthreads();
    #pragma unroll
    for (int i = ty; i < 32; i += 8)
        hiT[(size_t)(n0 + i) * K + k0 + tx] = __float2half(t[tx][i]);
}

// ---------------------------------------------------------------------------
// Warp-per-token windowed attention over fp16 qkv; fp16 hi/lo output.
// ---------------------------------------------------------------------------
__global__ __launch_bounds__(256) void attn_kernel(const float* __restrict__ x,
                                                   const float* __restrict__ w_width,
                                                   const float* __restrict__ b_width,
                                                   __half* __restrict__ att_hi,
                                                   __half* __restrict__ att_lo)
{
    const int gwarp = (blockIdx.x * blockDim.x + threadIdx.x) >> 5;
    const int lane = threadIdx.x & 31;
    if (gwarp >= NTOK) return;

    const int b = gwarp >> 13;
    const int l = gwarp & (LSEQ - 1);

    const __half* qkv = g_qkvh;

    float q[16];
    {
        const uint4* q4 = (const uint4*)(qkv + (size_t)gwarp * 3 * CDIM);
        #pragma unroll
        for (int i = 0; i < 2; i++) unpack8(q4[lane + 32 * i], q + 8 * i);
    }

    const float4* x4 = (const float4*)(x + (size_t)gwarp * CDIM);
    const float4* w4 = (const float4*)w_width;
    float wsum = 0.f;
    #pragma unroll
    for (int i = 0; i < 4; i++) {
        const float4 xv = x4[lane + 32 * i];
        const float4 wv = w4[lane + 32 * i];
        wsum += xv.x * wv.x + xv.y * wv.y + xv.z * wv.z + xv.w * wv.w;
    }
    #pragma unroll
    for (int o = 16; o > 0; o >>= 1) wsum += __shfl_xor_sync(0xffffffffu, wsum, o);
    const float width = 1.f / (1.f + expf(-(wsum + b_width[0]))) * (float)(KWIN - 1) + 1.f;

    float sc[KWIN];
    #pragma unroll
    for (int j = 0; j < KWIN; j++) {
        const int row = l + j - HALFK;
        float s = 0.f;
        if (row >= 0 && row < LSEQ) {
            const uint4* k4 = (const uint4*)(qkv + ((size_t)(b * LSEQ + row) * 3 + 1) * CDIM);
            #pragma unroll
            for (int i = 0; i < 2; i++) {
                float kf[8];
                unpack8(k4[lane + 32 * i], kf);
                #pragma unroll
                for (int t = 0; t < 8; t++) s += q[8 * i + t] * kf[t];
            }
        }
        #pragma unroll
        for (int o = 16; o > 0; o >>= 1) s += __shfl_xor_sync(0xffffffffu, s, o);
        sc[j] = s;
    }

    const float scale = 0.044194173824159216f;
    float mx = -1e30f;
    #pragma unroll
    for (int j = 0; j < KWIN; j++) {
        const float rel = fabsf((float)j - (float)HALFK);
        const float m = 1.f / (1.f + expf(-(width - rel) * 5.f));
        sc[j] = sc[j] * scale - (1.f - m) * 10000.f;
        mx = fmaxf(mx, sc[j]);
    }
    float denom = 0.f;
    #pragma unroll
    for (int j = 0; j < KWIN; j++) {
        sc[j] = expf(sc[j] - mx);
        denom += sc[j];
    }
    const float inv = 1.f / denom;

    float acc[16];
    {
        const uint4* vs = (const uint4*)(qkv + ((size_t)gwarp * 3 + 2) * CDIM);
        #pragma unroll
        for (int i = 0; i < 2; i++) unpack8(vs[lane + 32 * i], acc + 8 * i);
    }

    #pragma unroll
    for (int j = 0; j < KWIN; j++) {
        const int row = l + j - HALFK;
        if (row < 0 || row >= LSEQ) continue;
        const float a = sc[j] * inv;
        const uint4* v4 = (const uint4*)(qkv + ((size_t)(b * LSEQ + row) * 3 + 2) * CDIM);
        #pragma unroll
        for (int i = 0; i < 2; i++) {
            float vf[8];
            unpack8(v4[lane + 32 * i], vf);
            #pragma unroll
            for (int t = 0; t < 8; t++) acc[8 * i + t] += a * vf[t];
        }
    }

    uint4* hrow = (uint4*)(att_hi + (size_t)gwarp * CDIM);
    uint4* lrow = (uint4*)(att_lo + (size_t)gwarp * CDIM);
    #pragma unroll
    for (int i = 0; i < 2; i++) {
        uint4 uh, ul;
        __half2* hh = (__half2*)&uh;
        __half2* ll = (__half2*)&ul;
        #pragma unroll
        for (int t = 0; t < 4; t++) {
            const float f0 = acc[8 * i + 2 * t];
            const float f1 = acc[8 * i + 2 * t + 1];
            const __half h0 = __float2half(f0);
            const __half h1 = __float2half(f1);
            hh[t] = __halves2half2(h0, h1);
            ll[t] = __halves2half2(__float2half(f0 - __half2float(h0)),
                                   __float2half(f1 - __half2float(h1)));
        }
        hrow[lane + 32 * i] = uh;
        lrow[lane + 32 * i] = ul;
    }
}

// ---------------------------------------------------------------------------
extern "C" void kernel_launch(void* const* d_in, const int* in_sizes, int n_in,
                              void* d_out, int out_size)
{
    const float* x       = (const float*)d_in[0];
    const float* w_qkv   = (const float*)d_in[1];
    const float* w_width = (const float*)d_in[2];
    const float* b_width = (const float*)d_in[3];
    const float* w_out   = (const float*)d_in[4];
    float* out = (float*)d_out;

    __half* qkvh; cudaGetSymbolAddress((void**)&qkvh, g_qkvh);
    __half* xhi;  cudaGetSymbolAddress((void**)&xhi,  g_xhi);
    __half* xlo;  cudaGetSymbolAddress((void**)&xlo,  g_xlo);
    __half* ahi;  cudaGetSymbolAddress((void**)&ahi,  g_ahi);
    __half* alo;  cudaGetSymbolAddress((void**)&alo,  g_alo);
    __half* wqhi; cudaGetSymbolAddress((void**)&wqhi, g_wqhi);
    __half* wohi; cudaGetSymbolAddress((void**)&wohi, g_wohi);

    cudaFuncSetAttribute(gemm_mma<__half>, cudaFuncAttributeMaxDynamicSharedMemorySize, GEMM_SMEM);
    cudaFuncSetAttribute(gemm_mma<float>,  cudaFuncAttributeMaxDynamicSharedMemorySize, GEMM_SMEM);

    // 0) input splits
    split_kernel<<<(NTOK * CDIM) / (256 * 4), 256>>>(x, xhi, xlo);
    {
        dim3 g(3 * CDIM / 32, CDIM / 32);
        wsplit_kernel<<<g, dim3(32, 8)>>>(w_qkv, wqhi, CDIM, 3 * CDIM);
    }
    {
        dim3 g(CDIM / 32, CDIM / 32);
        wsplit_kernel<<<g, dim3(32, 8)>>>(w_out, wohi, CDIM, CDIM);
    }

    // 1) qkv = x @ w_qkv   (2-term fp16 split, fp16 output)
    {
        dim3 grid(3 * CDIM / 128, NTOK / 128);
        gemm_mma<__half><<<grid, 256, GEMM_SMEM>>>(xhi, xlo, wqhi, qkvh, 3 * CDIM);
    }

    // 2) fused windowed attention (fp16 qkv) -> att hi/lo (fp16 split)
    attn_kernel<<<NTOK / 8, 256>>>(x, w_width, b_width, ahi, alo);

    // 3) out = att @ w_out  (2-term fp16 split, fp32 output)
    {
        dim3 grid(CDIM / 128, NTOK / 128);
        gemm_mma<float><<<grid, 256, GEMM_SMEM>>>(ahi, alo, wohi, out, CDIM);
    }
}

// round 10
// speedup vs baseline: 1.5871x; 1.5871x over previous
#include <cuda_runtime.h>
#include <cuda_fp16.h>
#include <cstdint>

// Problem constants
#define BDIM 2
#define LSEQ 8192
#define CDIM 512
#define KWIN 17
#define HALFK 8
#define NTOK (BDIM * LSEQ)      // 16384

// ---------------------------------------------------------------------------
// Scratch (__device__ globals; no cudaMalloc allowed)
// ---------------------------------------------------------------------------
__device__ __half  g_qkvh[(size_t)NTOK * 3 * CDIM];    // 48 MB fp16 qkv
__device__ __half  g_xh[(size_t)NTOK * CDIM];          // x   -> fp16
__device__ __half  g_ah[(size_t)NTOK * CDIM];          // att -> fp16
__device__ __half  g_wqh[(size_t)3 * CDIM * CDIM];     // w_qkv^T fp16
__device__ __half  g_woh[(size_t)CDIM * CDIM];         // w_out^T fp16

// ---------------------------------------------------------------------------
// helpers
// ---------------------------------------------------------------------------
__device__ __forceinline__ uint32_t smem_u32(const void* p) {
    uint32_t a;
    asm("{ .reg .u64 t; cvta.to.shared.u64 t, %1; cvt.u32.u64 %0, t; }" : "=r"(a) : "l"(p));
    return a;
}
__device__ __forceinline__ void cp16(uint32_t dst, const void* src) {
    asm volatile("cp.async.cg.shared.global [%0], [%1], 16;" :: "r"(dst), "l"(src));
}
__device__ __forceinline__ void ldsm_x4(uint32_t* r, uint32_t addr) {
    asm volatile("ldmatrix.sync.aligned.m8n8.x4.shared.b16 {%0,%1,%2,%3}, [%4];"
                 : "=r"(r[0]), "=r"(r[1]), "=r"(r[2]), "=r"(r[3]) : "r"(addr));
}
__device__ __forceinline__ void ldsm_x2(uint32_t* r, uint32_t addr) {
    asm volatile("ldmatrix.sync.aligned.m8n8.x2.shared.b16 {%0,%1}, [%2];"
                 : "=r"(r[0]), "=r"(r[1]) : "r"(addr));
}
__device__ __forceinline__ void mma_f16(float* c, const uint32_t* a, const uint32_t* b) {
    asm volatile(
        "mma.sync.aligned.m16n8k16.row.col.f32.f16.f16.f32 "
        "{%0,%1,%2,%3}, {%4,%5,%6,%7}, {%8,%9}, {%0,%1,%2,%3};"
        : "+f"(c[0]), "+f"(c[1]), "+f"(c[2]), "+f"(c[3])
        : "r"(a[0]), "r"(a[1]), "r"(a[2]), "r"(a[3]), "r"(b[0]), "r"(b[1]));
}
#define CPWAIT(N) asm volatile("cp.async.wait_group %0;" :: "n"(N))

__device__ __forceinline__ void unpack8(uint4 u, float* f) {
    const __half2* h = (const __half2*)&u;
    #pragma unroll
    for (int t = 0; t < 4; t++) {
        float2 v = __half22float2(h[t]);
        f[2 * t] = v.x;
        f[2 * t + 1] = v.y;
    }
}

// ---------------------------------------------------------------------------
// Plain fp16 GEMM:  C = A @ B^T  (fp32 accum, OutT store)
// Block 128x128, 8 warps (2x4), warp 64x32.  BK=64 stages, 3 buffers,
// ONE __syncthreads per stage (load s+2 targets buffer consumed at s-1).
// 2 CTAs/SM.  PITCH=144 -> conflict-free ldmatrix.
// ---------------------------------------------------------------------------
#define GK       512
#define BK       64
#define NSTG     (GK / BK)          // 8
#define NBUF     3
#define PITCH    144
#define A_SZ     (128 * PITCH)      // 18432
#define STG_SZ   (2 * A_SZ)         // A | B = 36864
#define GEMM_SMEM (NBUF * STG_SZ)   // 110592

template <typename OutT>
__global__ __launch_bounds__(256, 2) void gemm_mma(
    const __half* __restrict__ A, const __half* __restrict__ B,
    OutT* __restrict__ C, int Ntot)
{
    extern __shared__ char smem[];
    const uint32_t sb = smem_u32(smem);
    const int tid  = threadIdx.x;
    const int wid  = tid >> 5;
    const int lane = tid & 31;
    const int bm = blockIdx.y * 128;
    const int bn = blockIdx.x * 128;
    const int warp_m = (wid >> 2) * 64;
    const int warp_n = (wid & 3) * 32;

    // loader: 128 rows x 8 chunks(16B) per matrix = 1024 chunks / 256 thr
    auto load_stage = [&](int s, int b) {
        const int k0 = s * BK;
        const uint32_t buf = sb + (uint32_t)b * STG_SZ;
        #pragma unroll
        for (int r = 0; r < 4; r++) {
            const int i   = tid + 256 * r;
            const int row = i >> 3;
            const int c16 = (i & 7) * 16;
            const uint32_t off = (uint32_t)(row * PITCH + c16);
            cp16(buf + off,        A + (size_t)(bm + row) * GK + k0 + (c16 >> 1));
            cp16(buf + A_SZ + off, B + (size_t)(bn + row) * GK + k0 + (c16 >> 1));
        }
        asm volatile("cp.async.commit_group;" ::: "memory");
    };

    float acc[4][4][4];
    #pragma unroll
    for (int mi = 0; mi < 4; mi++)
        #pragma unroll
        for (int ni = 0; ni < 4; ni++)
            #pragma unroll
            for (int f = 0; f < 4; f++) acc[mi][ni][f] = 0.f;

    const uint32_t aLane = (uint32_t)((warp_m + (lane & 15)) * PITCH + ((lane >> 4) & 1) * 16);
    const uint32_t bLane = (uint32_t)((warp_n + (lane & 7)) * PITCH + ((lane >> 3) & 1) * 16);

    load_stage(0, 0);
    load_stage(1, 1);

    for (int s = 0; s < NSTG; s++) {
        const int b = s % NBUF;
        if (s + 1 < NSTG) CPWAIT(1);
        else              CPWAIT(0);
        __syncthreads();
        // overlap next-next stage loads with this stage's MMAs
        if (s + 2 < NSTG) load_stage(s + 2, (s + 2) % NBUF);

        const uint32_t buf = sb + (uint32_t)b * STG_SZ;
        #pragma unroll
        for (int kk = 0; kk < 4; kk++) {
            const uint32_t ko = (uint32_t)(kk * 32);
            uint32_t ah[4][4], bh[4][2];
            #pragma unroll
            for (int mi = 0; mi < 4; mi++)
                ldsm_x4(ah[mi], buf + aLane + (uint32_t)(mi * 16 * PITCH) + ko);
            #pragma unroll
            for (int ni = 0; ni < 4; ni++)
                ldsm_x2(bh[ni], buf + A_SZ + bLane + (uint32_t)(ni * 8 * PITCH) + ko);
            #pragma unroll
            for (int mi = 0; mi < 4; mi++)
                #pragma unroll
                for (int ni = 0; ni < 4; ni++)
                    mma_f16(acc[mi][ni], ah[mi], bh[ni]);
        }
    }

    const int er = lane >> 2;
    const int ec = (lane & 3) * 2;
    #pragma unroll
    for (int mi = 0; mi < 4; mi++) {
        #pragma unroll
        for (int ni = 0; ni < 4; ni++) {
            OutT* p0 = C + (size_t)(bm + warp_m + mi * 16 + er) * Ntot + bn + warp_n + ni * 8 + ec;
            if constexpr (sizeof(OutT) == 2) {
                *(__half2*)p0 = __floats2half2_rn(acc[mi][ni][0], acc[mi][ni][1]);
                *(__half2*)(p0 + (size_t)8 * Ntot) = __floats2half2_rn(acc[mi][ni][2], acc[mi][ni][3]);
            } else {
                *(float2*)p0                      = make_float2(acc[mi][ni][0], acc[mi][ni][1]);
                *(float2*)(p0 + (size_t)8 * Ntot) = make_float2(acc[mi][ni][2], acc[mi][ni][3]);
            }
        }
    }
}

// ---------------------------------------------------------------------------
// fp32 -> fp16 convert, elementwise
// ---------------------------------------------------------------------------
__global__ __launch_bounds__(256) void tohalf_kernel(const float* __restrict__ src,
                                                     __half* __restrict__ dst)
{
    const size_t i = ((size_t)blockIdx.x * blockDim.x + threadIdx.x) * 4;
    float4 v = *(const float4*)(src + i);
    *(__half2*)(dst + i)     = __floats2half2_rn(v.x, v.y);
    *(__half2*)(dst + i + 2) = __floats2half2_rn(v.z, v.w);
}

// ---------------------------------------------------------------------------
// weight transpose: w[K,N] fp32 -> wT [N,K] fp16
// ---------------------------------------------------------------------------
__global__ __launch_bounds__(256) void wt_kernel(const float* __restrict__ w,
                                                 __half* __restrict__ wT,
                                                 int K, int N)
{
    __shared__ float t[32][33];
    const int k0 = blockIdx.y * 32;
    const int n0 = blockIdx.x * 32;
    const int tx = threadIdx.x, ty = threadIdx.y;
    #pragma unroll
    for (int i = ty; i < 32; i += 8)
        t[i][tx] = w[(size_t)(k0 + i) * N + n0 + tx];
    __syncthreads();
    #pragma unroll
    for (int i = ty; i < 32; i += 8)
        wT[(size_t)(n0 + i) * K + k0 + tx] = __float2half(t[tx][i]);
}

// ---------------------------------------------------------------------------
// Warp-per-token windowed attention over fp16 qkv; fp16 output (single)
// ---------------------------------------------------------------------------
__global__ __launch_bounds__(256) void attn_kernel(const float* __restrict__ x,
                                                   const float* __restrict__ w_width,
                                                   const float* __restrict__ b_width,
                                                   __half* __restrict__ att)
{
    const int gwarp = (blockIdx.x * blockDim.x + threadIdx.x) >> 5;
    const int lane = threadIdx.x & 31;
    if (gwarp >= NTOK) return;

    const int b = gwarp >> 13;
    const int l = gwarp & (LSEQ - 1);

    const __half* qkv = g_qkvh;

    float q[16];
    {
        const uint4* q4 = (const uint4*)(qkv + (size_t)gwarp * 3 * CDIM);
        #pragma unroll
        for (int i = 0; i < 2; i++) unpack8(q4[lane + 32 * i], q + 8 * i);
    }

    const float4* x4 = (const float4*)(x + (size_t)gwarp * CDIM);
    const float4* w4 = (const float4*)w_width;
    float wsum = 0.f;
    #pragma unroll
    for (int i = 0; i < 4; i++) {
        const float4 xv = x4[lane + 32 * i];
        const float4 wv = w4[lane + 32 * i];
        wsum += xv.x * wv.x + xv.y * wv.y + xv.z * wv.z + xv.w * wv.w;
    }
    #pragma unroll
    for (int o = 16; o > 0; o >>= 1) wsum += __shfl_xor_sync(0xffffffffu, wsum, o);
    const float width = 1.f / (1.f + expf(-(wsum + b_width[0]))) * (float)(KWIN - 1) + 1.f;

    float sc[KWIN];
    #pragma unroll
    for (int j = 0; j < KWIN; j++) {
        const int row = l + j - HALFK;
        float s = 0.f;
        if (row >= 0 && row < LSEQ) {
            const uint4* k4 = (const uint4*)(qkv + ((size_t)(b * LSEQ + row) * 3 + 1) * CDIM);
            #pragma unroll
            for (int i = 0; i < 2; i++) {
                float kf[8];
                unpack8(k4[lane + 32 * i], kf);
                #pragma unroll
                for (int t = 0; t < 8; t++) s += q[8 * i + t] * kf[t];
            }
        }
        #pragma unroll
        for (int o = 16; o > 0; o >>= 1) s += __shfl_xor_sync(0xffffffffu, s, o);
        sc[j] = s;
    }

    const float scale = 0.044194173824159216f;
    float mx = -1e30f;
    #pragma unroll
    for (int j = 0; j < KWIN; j++) {
        const float rel = fabsf((float)j - (float)HALFK);
        const float m = 1.f / (1.f + expf(-(width - rel) * 5.f));
        sc[j] = sc[j] * scale - (1.f - m) * 10000.f;
        mx = fmaxf(mx, sc[j]);
    }
    float denom = 0.f;
    #pragma unroll
    for (int j = 0; j < KWIN; j++) {
        sc[j] = expf(sc[j] - mx);
        denom += sc[j];
    }
    const float inv = 1.f / denom;

    float acc[16];
    {
        const uint4* vs = (const uint4*)(qkv + ((size_t)gwarp * 3 + 2) * CDIM);
        #pragma unroll
        for (int i = 0; i < 2; i++) unpack8(vs[lane + 32 * i], acc + 8 * i);
    }

    #pragma unroll
    for (int j = 0; j < KWIN; j++) {
        const int row = l + j - HALFK;
        if (row < 0 || row >= LSEQ) continue;
        const float a = sc[j] * inv;
        const uint4* v4 = (const uint4*)(qkv + ((size_t)(b * LSEQ + row) * 3 + 2) * CDIM);
        #pragma unroll
        for (int i = 0; i < 2; i++) {
            float vf[8];
            unpack8(v4[lane + 32 * i], vf);
            #pragma unroll
            for (int t = 0; t < 8; t++) acc[8 * i + t] += a * vf[t];
        }
    }

    uint4* arow = (uint4*)(att + (size_t)gwarp * CDIM);
    #pragma unroll
    for (int i = 0; i < 2; i++) {
        uint4 uh;
        __half2* hh = (__half2*)&uh;
        #pragma unroll
        for (int t = 0; t < 4; t++)
            hh[t] = __floats2half2_rn(acc[8 * i + 2 * t], acc[8 * i + 2 * t + 1]);
        arow[lane + 32 * i] = uh;
    }
}

// ---------------------------------------------------------------------------
extern "C" void kernel_launch(void* const* d_in, const int* in_sizes, int n_in,
                              void* d_out, int out_size)
{
    const float* x       = (const float*)d_in[0];
    const float* w_qkv   = (const float*)d_in[1];
    const float* w_width = (const float*)d_in[2];
    const float* b_width = (const float*)d_in[3];
    const float* w_out   = (const float*)d_in[4];
    float* out = (float*)d_out;

    __half* qkvh; cudaGetSymbolAddress((void**)&qkvh, g_qkvh);
    __half* xh;   cudaGetSymbolAddress((void**)&xh,   g_xh);
    __half* ah;   cudaGetSymbolAddress((void**)&ah,   g_ah);
    __half* wqh;  cudaGetSymbolAddress((void**)&wqh,  g_wqh);
    __half* woh;  cudaGetSymbolAddress((void**)&woh,  g_woh);

    cudaFuncSetAttribute(gemm_mma<__half>, cudaFuncAttributeMaxDynamicSharedMemorySize, GEMM_SMEM);
    cudaFuncSetAttribute(gemm_mma<float>,  cudaFuncAttributeMaxDynamicSharedMemorySize, GEMM_SMEM);

    // 0) conversions
    tohalf_kernel<<<(NTOK * CDIM) / (256 * 4), 256>>>(x, xh);
    {
        dim3 g(3 * CDIM / 32, CDIM / 32);
        wt_kernel<<<g, dim3(32, 8)>>>(w_qkv, wqh, CDIM, 3 * CDIM);
    }
    {
        dim3 g(CDIM / 32, CDIM / 32);
        wt_kernel<<<g, dim3(32, 8)>>>(w_out, woh, CDIM, CDIM);
    }

    // 1) qkv = x @ w_qkv   (fp16 in, fp16 out)
    {
        dim3 grid(3 * CDIM / 128, NTOK / 128);
        gemm_mma<__half><<<grid, 256, GEMM_SMEM>>>(xh, wqh, qkvh, 3 * CDIM);
    }

    // 2) fused windowed attention (fp16 qkv) -> att (fp16)
    attn_kernel<<<NTOK / 8, 256>>>(x, w_width, b_width, ah);

    // 3) out = att @ w_out  (fp16 in, fp32 out)
    {
        dim3 grid(CDIM / 128, NTOK / 128);
        gemm_mma<float><<<grid, 256, GEMM_SMEM>>>(ah, woh, out, CDIM);
    }
}